// round 15
// baseline (speedup 1.0000x reference)
#include <cuda_runtime.h>
#include <cuda_bf16.h>
#include <math.h>

// Problem constants
#define FD      128
#define K       15
#define FS      160
#define OV      40
#define NF      500
#define BATCH   32
#define NTOT    (NF * FS)          // 80000 samples per batch row
#define NFR     (BATCH * NF)       // 16000 frames total

// C = ln(10)/20 ; LOG_GAIN_LIMIT = 10*C ; GAIN_A = 6*C ; GAIN_B = 0
#define LOG_GAIN_LIMIT 1.1512925464970229f
#define GAIN_A         0.6907755278982137f
#define PI_F           3.14159265358979323846f

// ---------------------------------------------------------------------------
// Fused kernel: 256 threads / 8 warps per block, 8 consecutive frames per
// block (warp w owns frame fr0+w), grid = NFR/8 = 2000.
//
// Phase 1 (all threads): stage swizzled 17x128 weight matrix to shared;
//                        each warp stages its frame's x windows.
// Phase 2 (warps 0..2):  dots for 9 frames fr0-1 .. fr0+7 (R12 layout:
//                        8 lanes/frame, 4 frames/warp, broadcast LDS.128,
//                        in-thread epilogue) -> s_coef[9][16].
// Phase 3 (all warps):   R13 FIR + distributed tail recompute + crossfade,
//                        taps read directly from s_coef (broadcast LDS).
//
// This removes the second kernel launch and the g_coef global round-trip;
// the only duplicated work is re-computing each block-boundary frame's dots
// (9/8 per frame vs 1) against block-shared weights.
// ---------------------------------------------------------------------------
__global__ __launch_bounds__(256)
void fused_kernel(const float* __restrict__ x,
                  const float* __restrict__ features,
                  const int*   __restrict__ lags,
                  const float* __restrict__ ck_w, const float* __restrict__ ck_b,
                  const float* __restrict__ fg_w, const float* __restrict__ fg_b,
                  const float* __restrict__ gg_w, const float* __restrict__ gg_b,
                  float*       __restrict__ out)
{
    __shared__ __align__(16) float s_w[17 * 128];   // swizzled weights, 8.5 KB
    __shared__ __align__(16) float s_coef[9][16];   // coefs for fr0-1 .. fr0+7
    __shared__ __align__(16) float sh[8][388];      // per-warp FIR regions

    const int tid  = threadIdx.x;
    const int lane = tid & 31;
    const int warp = tid >> 5;
    const int fr0  = blockIdx.x * 8;
    const int fr   = fr0 + warp;                    // this warp's frame
    const int b    = fr / NF;
    const int f    = fr % NF;

    // ---- Phase 1a: stage weights with (q,seg) swizzle (all 256 threads) ----
    // s_w layout: dst4 = r*32 + q*8 + seg  holds w[r][seg*16 + q*4 .. +3]
    for (int o4 = tid; o4 < 544; o4 += 256) {
        const int r  = o4 >> 5;          // row 0..16 (0..14 ck, 15 fg, 16 gg)
        const int c4 = o4 & 31;          // float4 column within row
        float4 v;
        if (r < 15)       v = __ldg((const float4*)ck_w + r * 32 + c4);
        else if (r == 15) v = __ldg((const float4*)fg_w + c4);
        else              v = __ldg((const float4*)gg_w + c4);
        const int dst4 = r * 32 + (c4 & 3) * 8 + (c4 >> 2);
        *(float4*)(s_w + dst4 * 4) = v;
    }

    // ---- Phase 1b: stage this warp's x windows ----------------------------
    // sh[warp]: [0..174) xc ; [174..228) xp ; [228..388) pt
    const float* xb = x + (size_t)b * NTOT;
    float* s = sh[warp];
    const int base = f * FS - 7;                    // f*FS - PAD_L
    const int lag  = __ldg(lags + fr);

    #pragma unroll
    for (int t = lane; t < 174; t += 32) {
        const int idx = base - lag + t;
        s[t] = (idx >= 0 && idx < NTOT) ? __ldg(xb + idx) : 0.f;
    }
    if (f > 0) {
        const int lagp = __ldg(lags + fr - 1);
        #pragma unroll
        for (int t = lane; t < 54; t += 32) {
            const int idx = base - lagp + t;
            s[174 + t] = (idx >= 0) ? __ldg(xb + idx) : 0.f;
        }
    }
    #pragma unroll
    for (int t = lane; t < FS; t += 32)
        s[228 + t] = __ldg(xb + f * FS + t);

    __syncthreads();

    // ---- Phase 2: dots for 9 frames on warps 0..2 --------------------------
    if (warp < 3) {
        const int j   = lane >> 3;                  // frame slot within warp
        const int seg = lane & 7;                   // 16-feature segment
        const int i   = warp * 4 + j;               // 0..11 ; valid if i < 9
        int fi = fr0 - 1 + (i > 8 ? 8 : i);         // clamp keeps loads in-bounds
        if (fi < 0) fi = 0;
        if (fi >= NFR) fi = NFR - 1;

        const float4* fp = (const float4*)(features + (size_t)fi * FD) + seg * 4;
        const float4 f0 = __ldg(fp + 0), f1 = __ldg(fp + 1),
                     f2 = __ldg(fp + 2), f3 = __ldg(fp + 3);

        float acc[17];
        #pragma unroll
        for (int r = 0; r < 17; r++) {
            const float4* wr = (const float4*)(s_w + r * 128) + seg;
            const float4 w0 = wr[0], w1 = wr[8], w2 = wr[16], w3 = wr[24];
            acc[r]  = f0.x*w0.x + f0.y*w0.y + f0.z*w0.z + f0.w*w0.w;
            acc[r] += f1.x*w1.x + f1.y*w1.y + f1.z*w1.z + f1.w*w1.w;
            acc[r] += f2.x*w2.x + f2.y*w2.y + f2.z*w2.z + f2.w*w2.w;
            acc[r] += f3.x*w3.x + f3.y*w3.y + f3.z*w3.z + f3.w*w3.w;
        }
        #pragma unroll
        for (int r = 0; r < 17; r++) {
            acc[r] += __shfl_xor_sync(0xffffffffu, acc[r], 1);
            acc[r] += __shfl_xor_sync(0xffffffffu, acc[r], 2);
            acc[r] += __shfl_xor_sync(0xffffffffu, acc[r], 4);
        }
        if (seg == 0 && i < 9) {
            float d[15], ss = 0.f;
            #pragma unroll
            for (int r = 0; r < 15; r++) {
                d[r] = acc[r] + __ldg(ck_b + r);
                ss += d[r] * d[r];
            }
            const float fgd = acc[15] + __ldg(fg_b);
            const float ggd = acc[16] + __ldg(gg_b);
            const float gs  = __expf(LOG_GAIN_LIMIT - fmaxf(fgd, 0.f))
                            / (1e-6f + sqrtf(ss));
            const float gge = __expf(GAIN_A * tanhf(ggd));
            float4* dst = (float4*)s_coef[i];
            dst[0] = make_float4(d[0]*gs,  d[1]*gs,  d[2]*gs,  d[3]*gs);
            dst[1] = make_float4(d[4]*gs,  d[5]*gs,  d[6]*gs,  d[7]*gs);
            dst[2] = make_float4(d[8]*gs,  d[9]*gs,  d[10]*gs, d[11]*gs);
            dst[3] = make_float4(d[12]*gs, d[13]*gs, d[14]*gs, gge);
        }
    }
    __syncthreads();

    // ---- Phase 3: FIR + distributed tail + crossfade (R13 body) ------------
    const float* cc = s_coef[warp + 1];     // current frame's coefs
    const float* cp = s_coef[warp];         // previous frame's coefs

    float tap[15];
    #pragma unroll
    for (int k = 0; k < 15; k++) tap[k] = cc[k];
    const float gg = cc[15];

    float xv[19];
    #pragma unroll
    for (int j = 0; j < 19; j++) xv[j] = s[5 * lane + j];

    float res[5];
    #pragma unroll
    for (int i = 0; i < 5; i++) {
        float conv = 0.f;
        #pragma unroll
        for (int k = 0; k < 15; k++)
            conv = fmaf(xv[i + k], tap[k], conv);
        res[i] = gg * (conv + s[228 + 5 * lane + i]);
    }

    // distributed tail recompute: lanes 0..19, outputs o = 2*lane, 2*lane+1
    float t0 = 0.f, t1 = 0.f, w20 = 0.f, w21 = 0.f;
    if (lane < 20) {
        const int o = 2 * lane;
        w20 = 0.5f + 0.5f * __cosf((o + 0.5f) * (PI_F / OV));
        w21 = 0.5f + 0.5f * __cosf((o + 1.5f) * (PI_F / OV));
        if (f > 0) {
            float tp[15];
            #pragma unroll
            for (int k = 0; k < 15; k++) tp[k] = cp[k];
            const float ggp = cp[15];
            float xw[16];
            #pragma unroll
            for (int j = 0; j < 16; j++) xw[j] = s[174 + o + j];
            float c0 = 0.f, c1 = 0.f;
            #pragma unroll
            for (int k = 0; k < 15; k++) {
                c0 = fmaf(xw[k],     tp[k], c0);
                c1 = fmaf(xw[k + 1], tp[k], c1);
            }
            // prev frame's pass-through at l=FS+o equals x[f*FS + o] = pt[o]
            t0 = ggp * (c0 + s[228 + o]);
            t1 = ggp * (c1 + s[228 + o + 1]);
        }
    }
    __syncwarp();                 // all xv/xw reads done before reusing xc region
    if (lane < 20) {
        s[2 * lane]          = t0;
        s[2 * lane + 1]      = t1;
        s[40 + 2 * lane]     = w20;
        s[40 + 2 * lane + 1] = w21;
    }
    __syncwarp();

    // head blend (o < 40): lanes 0..7 own those outputs
    if (lane < 8) {
        #pragma unroll
        for (int i = 0; i < 5; i++) {
            const int j5 = 5 * lane + i;
            const float w2 = s[40 + j5];
            res[i] = res[i] * (1.f - w2) + s[j5] * w2;   // win1 = 1 - win2
        }
    }

    // bounce through shared for coalesced stores
    __syncwarp();
    #pragma unroll
    for (int i = 0; i < 5; i++) s[5 * lane + i] = res[i];
    __syncwarp();

    float* op = out + (size_t)b * NTOT + f * FS;
    #pragma unroll
    for (int i = 0; i < 5; i++)
        op[lane + 32 * i] = s[lane + 32 * i];
}

extern "C" void kernel_launch(void* const* d_in, const int* in_sizes, int n_in,
                              void* d_out, int out_size)
{
    const float* x        = (const float*)d_in[0];
    const float* features = (const float*)d_in[1];
    const int*   lags     = (const int*)  d_in[2];
    const float* ck_w     = (const float*)d_in[3];
    const float* ck_b     = (const float*)d_in[4];
    const float* fg_w     = (const float*)d_in[5];
    const float* fg_b     = (const float*)d_in[6];
    const float* gg_w     = (const float*)d_in[7];
    const float* gg_b     = (const float*)d_in[8];

    fused_kernel<<<NFR / 8, 256>>>(x, features, lags, ck_w, ck_b,
                                   fg_w, fg_b, gg_w, gg_b, (float*)d_out);
}

// round 16
// speedup vs baseline: 1.0795x; 1.0795x over previous
#include <cuda_runtime.h>
#include <cuda_bf16.h>
#include <math.h>

// Problem constants
#define FD      128
#define K       15
#define FS      160
#define OV      40
#define NF      500
#define BATCH   32
#define NTOT    (NF * FS)          // 80000 samples per batch row
#define NFR     (BATCH * NF)       // 16000 frames total

// C = ln(10)/20 ; LOG_GAIN_LIMIT = 10*C ; GAIN_A = 6*C ; GAIN_B = 0
#define LOG_GAIN_LIMIT 1.1512925464970229f
#define GAIN_A         0.6907755278982137f
#define PI_F           3.14159265358979323846f

// ---------------------------------------------------------------------------
// Fused kernel v2: 256 threads / 8 warps, 8 consecutive frames per block,
// grid = NFR/8 = 2000. Phases OVERLAP instead of serializing:
//   warps 0-2 : load features -> stage swizzled weights -> bar.sync(1,96)
//               -> dots for 9 frames (fr0-1 .. fr0+7) -> s_coef[9][16]
//   warps 3-7 : stage x windows for ALL 8 frames (sh[8][388])
//   __syncthreads()  (the only block-wide barrier)
//   all warps : R13 FIR + distributed tail recompute + crossfade + store
// ---------------------------------------------------------------------------
__global__ __launch_bounds__(256, 5)
void fused_kernel(const float* __restrict__ x,
                  const float* __restrict__ features,
                  const int*   __restrict__ lags,
                  const float* __restrict__ ck_w, const float* __restrict__ ck_b,
                  const float* __restrict__ fg_w, const float* __restrict__ fg_b,
                  const float* __restrict__ gg_w, const float* __restrict__ gg_b,
                  float*       __restrict__ out)
{
    __shared__ __align__(16) float s_w[17 * 128];   // swizzled weights, 8.5 KB
    __shared__ __align__(16) float s_coef[9][16];   // coefs fr0-1 .. fr0+7
    __shared__ __align__(16) float sh[8][388];      // per-frame FIR regions

    const int tid  = threadIdx.x;
    const int lane = tid & 31;
    const int warp = tid >> 5;
    const int fr0  = blockIdx.x * 8;

    if (warp < 3) {
        // ---- dots pipeline (96 threads) -----------------------------------
        const int j   = lane >> 3;                  // frame slot within warp
        const int seg = lane & 7;                   // 16-feature segment
        const int i   = warp * 4 + j;               // 0..11 ; valid if i < 9
        int fi = fr0 - 1 + (i > 8 ? 8 : i);         // clamp keeps loads in-bounds
        if (fi < 0) fi = 0;

        // features first (latency overlapped with weight staging below)
        const float4* fp = (const float4*)(features + (size_t)fi * FD) + seg * 4;
        const float4 f0 = __ldg(fp + 0), f1 = __ldg(fp + 1),
                     f2 = __ldg(fp + 2), f3 = __ldg(fp + 3);

        // stage weights with (q,seg) swizzle: dst4 = r*32 + q*8 + seg
        for (int o4 = tid; o4 < 544; o4 += 96) {
            const int r  = o4 >> 5;          // row 0..16
            const int c4 = o4 & 31;          // float4 column within row
            float4 v;
            if (r < 15)       v = __ldg((const float4*)ck_w + r * 32 + c4);
            else if (r == 15) v = __ldg((const float4*)fg_w + c4);
            else              v = __ldg((const float4*)gg_w + c4);
            const int dst4 = r * 32 + (c4 & 3) * 8 + (c4 >> 2);
            *(float4*)(s_w + dst4 * 4) = v;
        }
        asm volatile("bar.sync 1, 96;" ::: "memory");   // warps 0-2 only

        float acc[17];
        #pragma unroll
        for (int r = 0; r < 17; r++) {
            const float4* wr = (const float4*)(s_w + r * 128) + seg;
            const float4 w0 = wr[0], w1 = wr[8], w2 = wr[16], w3 = wr[24];
            acc[r]  = f0.x*w0.x + f0.y*w0.y + f0.z*w0.z + f0.w*w0.w;
            acc[r] += f1.x*w1.x + f1.y*w1.y + f1.z*w1.z + f1.w*w1.w;
            acc[r] += f2.x*w2.x + f2.y*w2.y + f2.z*w2.z + f2.w*w2.w;
            acc[r] += f3.x*w3.x + f3.y*w3.y + f3.z*w3.z + f3.w*w3.w;
        }
        #pragma unroll
        for (int r = 0; r < 17; r++) {
            acc[r] += __shfl_xor_sync(0xffffffffu, acc[r], 1);
            acc[r] += __shfl_xor_sync(0xffffffffu, acc[r], 2);
            acc[r] += __shfl_xor_sync(0xffffffffu, acc[r], 4);
        }
        if (seg == 0 && i < 9) {
            float d[15], ss = 0.f;
            #pragma unroll
            for (int r = 0; r < 15; r++) {
                d[r] = acc[r] + __ldg(ck_b + r);
                ss += d[r] * d[r];
            }
            const float fgd = acc[15] + __ldg(fg_b);
            const float ggd = acc[16] + __ldg(gg_b);
            const float gs  = __expf(LOG_GAIN_LIMIT - fmaxf(fgd, 0.f))
                            / (1e-6f + sqrtf(ss));
            const float gge = __expf(GAIN_A * tanhf(ggd));
            float4* dst = (float4*)s_coef[i];
            dst[0] = make_float4(d[0]*gs,  d[1]*gs,  d[2]*gs,  d[3]*gs);
            dst[1] = make_float4(d[4]*gs,  d[5]*gs,  d[6]*gs,  d[7]*gs);
            dst[2] = make_float4(d[8]*gs,  d[9]*gs,  d[10]*gs, d[11]*gs);
            dst[3] = make_float4(d[12]*gs, d[13]*gs, d[14]*gs, gge);
        }
    } else {
        // ---- stage x windows for all 8 frames (160 threads) ---------------
        const int st = tid - 96;                    // 0..159
        #pragma unroll 1
        for (int jf = 0; jf < 8; jf++) {
            const int frj = fr0 + jf;
            const int bj  = frj / NF;
            const int fj  = frj - bj * NF;
            const float* xbj = x + (size_t)bj * NTOT;
            float* sj = sh[jf];
            const int basej = fj * FS - 7;
            const int lagj  = __ldg(lags + frj);

            if (fj >= 2 && fj <= 498) {             // fully in-range fast path
                const float* src = xbj + (basej - lagj);
                #pragma unroll
                for (int t = st; t < 174; t += 160) sj[t] = __ldg(src + t);
                const int lagp = __ldg(lags + frj - 1);
                if (st < 54) sj[174 + st] = __ldg(xbj + basej - lagp + st);
                sj[228 + st] = __ldg(xbj + fj * FS + st);
            } else {                                 // fj in {0,1,499}
                #pragma unroll
                for (int t = st; t < 174; t += 160) {
                    const int idx = basej - lagj + t;
                    sj[t] = (idx >= 0 && idx < NTOT) ? __ldg(xbj + idx) : 0.f;
                }
                if (fj > 0 && st < 54) {
                    const int lagp = __ldg(lags + frj - 1);
                    const int idx = basej - lagp + st;
                    sj[174 + st] = (idx >= 0) ? __ldg(xbj + idx) : 0.f;
                }
                sj[228 + st] = __ldg(xbj + fj * FS + st);
            }
        }
    }
    __syncthreads();

    // ---- Phase 3: FIR + distributed tail + crossfade (R13 body) ------------
    const int fr = fr0 + warp;
    const int b  = fr / NF;
    const int f  = fr - b * NF;
    float* s = sh[warp];

    const float* cc = s_coef[warp + 1];     // current frame's coefs
    const float* cp = s_coef[warp];         // previous frame's coefs

    float tap[15];
    #pragma unroll
    for (int k = 0; k < 15; k++) tap[k] = cc[k];
    const float gg = cc[15];

    float xv[19];
    #pragma unroll
    for (int j = 0; j < 19; j++) xv[j] = s[5 * lane + j];

    float res[5];
    #pragma unroll
    for (int i = 0; i < 5; i++) {
        float conv = 0.f;
        #pragma unroll
        for (int k = 0; k < 15; k++)
            conv = fmaf(xv[i + k], tap[k], conv);
        res[i] = gg * (conv + s[228 + 5 * lane + i]);
    }

    // distributed tail recompute: lanes 0..19, outputs o = 2*lane, 2*lane+1
    float t0 = 0.f, t1 = 0.f, w20 = 0.f, w21 = 0.f;
    if (lane < 20) {
        const int o = 2 * lane;
        w20 = 0.5f + 0.5f * __cosf((o + 0.5f) * (PI_F / OV));
        w21 = 0.5f + 0.5f * __cosf((o + 1.5f) * (PI_F / OV));
        if (f > 0) {
            float tp[15];
            #pragma unroll
            for (int k = 0; k < 15; k++) tp[k] = cp[k];
            const float ggp = cp[15];
            float xw[16];
            #pragma unroll
            for (int j = 0; j < 16; j++) xw[j] = s[174 + o + j];
            float c0 = 0.f, c1 = 0.f;
            #pragma unroll
            for (int k = 0; k < 15; k++) {
                c0 = fmaf(xw[k],     tp[k], c0);
                c1 = fmaf(xw[k + 1], tp[k], c1);
            }
            // prev frame's pass-through at l=FS+o equals x[f*FS + o] = pt[o]
            t0 = ggp * (c0 + s[228 + o]);
            t1 = ggp * (c1 + s[228 + o + 1]);
        }
    }
    __syncwarp();                 // all xv/xw reads done before reusing xc region
    if (lane < 20) {
        s[2 * lane]          = t0;
        s[2 * lane + 1]      = t1;
        s[40 + 2 * lane]     = w20;
        s[40 + 2 * lane + 1] = w21;
    }
    __syncwarp();

    // head blend (o < 40): lanes 0..7 own those outputs
    if (lane < 8) {
        #pragma unroll
        for (int i = 0; i < 5; i++) {
            const int j5 = 5 * lane + i;
            const float w2 = s[40 + j5];
            res[i] = res[i] * (1.f - w2) + s[j5] * w2;   // win1 = 1 - win2
        }
    }

    // bounce through shared for coalesced stores
    __syncwarp();
    #pragma unroll
    for (int i = 0; i < 5; i++) s[5 * lane + i] = res[i];
    __syncwarp();

    float* op = out + (size_t)b * NTOT + f * FS;
    #pragma unroll
    for (int i = 0; i < 5; i++)
        op[lane + 32 * i] = s[lane + 32 * i];
}

extern "C" void kernel_launch(void* const* d_in, const int* in_sizes, int n_in,
                              void* d_out, int out_size)
{
    const float* x        = (const float*)d_in[0];
    const float* features = (const float*)d_in[1];
    const int*   lags     = (const int*)  d_in[2];
    const float* ck_w     = (const float*)d_in[3];
    const float* ck_b     = (const float*)d_in[4];
    const float* fg_w     = (const float*)d_in[5];
    const float* fg_b     = (const float*)d_in[6];
    const float* gg_w     = (const float*)d_in[7];
    const float* gg_b     = (const float*)d_in[8];

    fused_kernel<<<NFR / 8, 256>>>(x, features, lags, ck_w, ck_b,
                                   fg_w, fg_b, gg_w, gg_b, (float*)d_out);
}